// round 9
// baseline (speedup 1.0000x reference)
#include <cuda_runtime.h>
#include <cuda_fp16.h>
#include <cstdint>
#include <math.h>

#define NMAX 262144
#define GMAX 8192
#define EDIM 118
#define FDIM 128
#define KTAB 1024         // intervals per branch (KTAB+1 grid rows)
#define WPITCH 129        // odd pitch -> conflict-free smem dot reads
#define SCAN_ILP 8

// ---------------- scratch (device globals; no allocation) ----------------
__device__ float  g_y[NMAX];
__device__ float  g_denom[GMAX];
__device__ float  g_dot[EDIM * 2];
__device__ float  g_amax;
__device__ float  g_lin[2 * FDIM];                   // F'(0) per branch
__device__ __half g_tabh[2][KTAB + 1][FDIM];         // residual G(|att|), fp16 rows (256B)

// ---------------- helpers ----------------
__device__ __forceinline__ float s1f(float x) {      // silu(x) - x/2, O(x^2), no cancellation
    return 0.5f * x * tanhf(0.5f * x);
}

// ---------------- kernel: zero denom + amax + dot table ----------------
__global__ void k_prep(const float* __restrict__ Wq, const float* __restrict__ Wk,
                       const float* __restrict__ psi, int G) {
    __shared__ float sk[256];
    __shared__ float smax[8];
    int t = threadIdx.x;
    for (int i = t; i < G; i += 256) g_denom[i] = 0.f;
    sk[t] = Wk[t];
    float m = 0.f;
    for (int i = t; i < G; i += 256) m = fmaxf(m, fabsf(psi[i]));
#pragma unroll
    for (int o = 16; o; o >>= 1) m = fmaxf(m, __shfl_xor_sync(0xffffffffu, m, o));
    if ((t & 31) == 0) smax[t >> 5] = m;
    __syncthreads();
    if (t == 0) {
        float mm = 1e-12f;
        for (int i = 0; i < 8; ++i) mm = fmaxf(mm, smax[i]);
        g_amax = mm;
    }
    if (t < EDIM) {
        float a0 = 0.f, a1 = 0.f;
#pragma unroll 8
        for (int f = 0; f < FDIM; ++f) {
            float w = Wq[f * EDIM + t];
            a0 = fmaf(w, sk[f], a0);
            a1 = fmaf(w, sk[FDIM + f], a1);
        }
        g_dot[t * 2 + 0] = a0;
        g_dot[t * 2 + 1] = a1;
    }
}

// ---------------- kernel: 8-deep streaming scan, OR-tree filter ---------------
__global__ void __launch_bounds__(512)
k_scan(const uint4* __restrict__ oh4, const float* __restrict__ psi,
       const int* __restrict__ bs, int nvec) {
    int stride = gridDim.x * blockDim.x;
    for (int base = blockIdx.x * blockDim.x + threadIdx.x; base < nvec;
         base += SCAN_ILP * stride) {
        uint4 v[SCAN_ILP];
        int ii[SCAN_ILP];
#pragma unroll
        for (int u = 0; u < SCAN_ILP; ++u) {
            ii[u] = base + u * stride;
            if (ii[u] < nvec) v[u] = __ldcs(oh4 + ii[u]);
            else v[u] = make_uint4(0u, 0u, 0u, 0u);
        }
        unsigned orv[SCAN_ILP];
        unsigned any = 0u;
#pragma unroll
        for (int u = 0; u < SCAN_ILP; ++u) {
            orv[u] = (v[u].x | v[u].y) | (v[u].z | v[u].w);
            any |= orv[u];
        }
        if (!any) continue;
#pragma unroll
        for (int u = 0; u < SCAN_ILP; ++u) {
            if (orv[u]) {
                unsigned idx4 = 4u * (unsigned)ii[u];
                unsigned w[4] = {v[u].x, v[u].y, v[u].z, v[u].w};
#pragma unroll
                for (int c = 0; c < 4; ++c) {
                    if (w[c]) {
                        unsigned f = idx4 + (unsigned)c;
                        unsigned atom = f / 118u;
                        unsigned e = f - atom * 118u;
                        int g = bs[atom];
                        float p = psi[g];
                        int r = (p < 0.f) ? 1 : 0;
                        float qk = g_dot[e * 2 + r] * 0.08838834764831845f; // 1/sqrt(128)
                        float y = (qk > 20.f) ? qk : log1pf(expf(qk));
                        g_y[atom] = y;
                        atomicAdd(&g_denom[g], y);
                    }
                }
            }
        }
    }
}

// ---------------- kernel: two-phase residual table + F'(0) --------------------
//   hlin = W1@wv;  h(a) = 0.5a*hlin + W1@s1(a*wv)
//   F(a) - a*F1 = W2 @ [ 0.5*(W1@s1(a*wv)) + s1(h(a)) ]
//   F1 = wv + 0.25*(W2@hlin)
__global__ void k_tab(const float* __restrict__ Wv, const float* __restrict__ W1,
                      const float* __restrict__ W2) {
    extern __shared__ float sm[];
    float* sW  = sm;                       // [128][WPITCH] (W1, then W2)
    float* swv = sW + FDIM * WPITCH;       // [128]
    float* shl = swv + FDIM;               // [128] hlin
    float* sSv = shl + FDIM;               // [8][128] s1(a_u*wv)
    float* sB  = sSv + 8 * FDIM;           // [8][128] bracket
    int t = threadIdx.x;
    int b = blockIdx.x;
    int r = (b >= 129) ? 1 : 0;
    int i0 = (b - r * 129) * 8;
    float sgn = r ? -1.f : 1.f;

    const float4* W1v = (const float4*)W1;
    for (int i = t; i < FDIM * 32; i += 128) {
        int row = i >> 5, c = (i & 31) * 4;
        float4 v = W1v[i];
        float* p = sW + row * WPITCH + c;
        p[0] = v.x; p[1] = v.y; p[2] = v.z; p[3] = v.w;
    }
    float wv = Wv[r * FDIM + t];
    swv[t] = wv;
    __syncthreads();

    const float* wrow = sW + t * WPITCH;
    float hlin;
    {
        float d0 = 0.f, d1 = 0.f, d2 = 0.f, d3 = 0.f;
#pragma unroll
        for (int k = 0; k < FDIM; k += 4) {
            d0 = fmaf(wrow[k],     swv[k],     d0);
            d1 = fmaf(wrow[k + 1], swv[k + 1], d1);
            d2 = fmaf(wrow[k + 2], swv[k + 2], d2);
            d3 = fmaf(wrow[k + 3], swv[k + 3], d3);
        }
        hlin = (d0 + d1) + (d2 + d3);
        shl[t] = hlin;
    }
    float amax = g_amax;
    float av[8];
#pragma unroll
    for (int u = 0; u < 8; ++u) {
        int i = i0 + u;
        float mag = (i == 0) ? (amax * (1.f / 8192.f)) : (amax * (float)i * (1.f / KTAB));
        av[u] = sgn * mag;
        sSv[u * FDIM + t] = s1f(av[u] * wv);
    }
    __syncthreads();

    for (int u = 0; u < 8; ++u) {
        if (i0 + u > KTAB) break;
        const float* sv = sSv + u * FDIM;
        float d0 = 0.f, d1 = 0.f, d2 = 0.f, d3 = 0.f;
#pragma unroll
        for (int k = 0; k < FDIM; k += 4) {
            d0 = fmaf(wrow[k],     sv[k],     d0);
            d1 = fmaf(wrow[k + 1], sv[k + 1], d1);
            d2 = fmaf(wrow[k + 2], sv[k + 2], d2);
            d3 = fmaf(wrow[k + 3], sv[k + 3], d3);
        }
        float tt = (d0 + d1) + (d2 + d3);
        float h = fmaf(0.5f * av[u], hlin, tt);
        sB[u * FDIM + t] = fmaf(0.5f, tt, s1f(h));
    }
    __syncthreads();

    const float4* W2v = (const float4*)W2;
    for (int i = t; i < FDIM * 32; i += 128) {
        int row = i >> 5, c = (i & 31) * 4;
        float4 v = W2v[i];
        float* p = sW + row * WPITCH + c;
        p[0] = v.x; p[1] = v.y; p[2] = v.z; p[3] = v.w;
    }
    __syncthreads();

    if (i0 == 0) {
        float d0 = 0.f, d1 = 0.f, d2 = 0.f, d3 = 0.f;
#pragma unroll
        for (int k = 0; k < FDIM; k += 4) {
            d0 = fmaf(wrow[k],     shl[k],     d0);
            d1 = fmaf(wrow[k + 1], shl[k + 1], d1);
            d2 = fmaf(wrow[k + 2], shl[k + 2], d2);
            d3 = fmaf(wrow[k + 3], shl[k + 3], d3);
        }
        g_lin[r * FDIM + t] = fmaf(0.25f, (d0 + d1) + (d2 + d3), wv);
    }
    for (int u = 0; u < 8; ++u) {
        int i = i0 + u;
        if (i > KTAB) break;
        const float* bv = sB + u * FDIM;
        float e0 = 0.f, e1 = 0.f, e2 = 0.f, e3 = 0.f;
#pragma unroll
        for (int k = 0; k < FDIM; k += 4) {
            e0 = fmaf(wrow[k],     bv[k],     e0);
            e1 = fmaf(wrow[k + 1], bv[k + 1], e1);
            e2 = fmaf(wrow[k + 2], bv[k + 2], e2);
            e3 = fmaf(wrow[k + 3], bv[k + 3], e3);
        }
        float resid = (e0 + e1) + (e2 + e3);
        g_tabh[r][i][t] = __float2half(resid / (av[u] * av[u]));
    }
}

// ---------------- kernel: fused att + table lookup + linear epilogue ----------
__global__ void __launch_bounds__(256)
k_out(const float* __restrict__ psi, const int* __restrict__ bs,
      float* __restrict__ out, int N) {
    __shared__ float sF1[2 * FDIM];
    __shared__ float sAtt[8];
    __shared__ float s_scale;
    int tid = threadIdx.x;
    int base = blockIdx.x * 8;
    sF1[tid] = g_lin[tid];
    if (tid == 0) s_scale = (float)KTAB / g_amax;
    if (tid < 8) {
        int n = base + tid;
        float att = 0.f;
        if (n < N) {
            int g = bs[n];
            float p = psi[g];
            att = p * g_y[n] / (g_denom[g] + 1e-6f);
        }
        sAtt[tid] = att;
    }
    __syncthreads();
    int n = base + (tid >> 5);
    if (n >= N) return;
    int lane = tid & 31;
    float att = sAtt[tid >> 5];
    int r = (att < 0.f) ? 1 : 0;
    float x = fabsf(att) * s_scale;
    int j = __float2int_rn(x);
    if (j > KTAB) j = KTAB;
    const uint2* rowp = (const uint2*)(&g_tabh[r][j][0]);
    uint2 raw = __ldg(rowp + lane);            // 4 halves = features 4*lane..+3
    float2 g01 = __half22float2(*(const __half2*)&raw.x);
    float2 g23 = __half22float2(*(const __half2*)&raw.y);
    float4 f1 = ((const float4*)(sF1 + r * FDIM))[lane];
    float att2 = att * att;
    float4 o;
    o.x = fmaf(att, f1.x, att2 * g01.x);
    o.y = fmaf(att, f1.y, att2 * g01.y);
    o.z = fmaf(att, f1.z, att2 * g23.x);
    o.w = fmaf(att, f1.w, att2 * g23.y);
    __stcs((float4*)out + (size_t)n * 32 + lane, o);
}

// ---------------- launch ----------------
extern "C" void kernel_launch(void* const* d_in, const int* in_sizes, int n_in,
                              void* d_out, int out_size) {
    const float* oh  = (const float*)d_in[0];
    const float* psi = (const float*)d_in[1];
    const float* Wq  = (const float*)d_in[2];
    const float* Wk  = (const float*)d_in[3];
    const float* Wv  = (const float*)d_in[4];
    const float* W1  = (const float*)d_in[5];
    const float* W2  = (const float*)d_in[6];
    const int*   bs  = (const int*)d_in[7];
    int N = in_sizes[7];
    int G = in_sizes[1];
    float* out = (float*)d_out;

    const int tab_smem = (FDIM * WPITCH + 2 * FDIM + 16 * FDIM) * 4;   // ~75 KB
    cudaFuncSetAttribute(k_tab, cudaFuncAttributeMaxDynamicSharedMemorySize, tab_smem);

    int nvec = (N * EDIM) / 4;                // N*118 divisible by 4

    k_prep<<<1, 256>>>(Wq, Wk, psi, G);
    k_scan<<<592, 512>>>((const uint4*)oh, psi, bs, nvec);
    k_tab<<<258, 128, tab_smem>>>(Wv, W1, W2);
    k_out<<<(N + 7) / 8, 256>>>(psi, bs, out, N);
}

// round 10
// speedup vs baseline: 1.2104x; 1.2104x over previous
#include <cuda_runtime.h>
#include <cuda_fp16.h>
#include <cstdint>
#include <math.h>

#define NMAX 262144
#define GMAX 8192
#define EDIM 118
#define FDIM 128
#define KTAB 1024         // intervals per branch (KTAB+1 grid rows)
#define WPITCH 129        // odd pitch -> conflict-free smem dot reads

// ---------------- scratch (device globals; no allocation) ----------------
__device__ float  g_y[NMAX];
__device__ float  g_att[NMAX];
__device__ float  g_denom[GMAX];
__device__ float  g_dot[EDIM * 2];
__device__ float  g_amax;
__device__ float  g_lin[2 * FDIM];                   // F'(0) per branch
__device__ __half g_tabh[2][KTAB + 1][FDIM];         // residual G(|att|), fp16 rows (256B)

// ---------------- helpers ----------------
__device__ __forceinline__ float s1f(float x) {      // silu(x) - x/2, O(x^2), no cancellation
    return 0.5f * x * tanhf(0.5f * x);
}

// ---------------- kernel: zero denom + amax + dot table ----------------
__global__ void k_prep(const float* __restrict__ Wq, const float* __restrict__ Wk,
                       const float* __restrict__ psi, int G) {
    __shared__ float sk[256];
    __shared__ float smax[8];
    int t = threadIdx.x;
    for (int i = t; i < G; i += 256) g_denom[i] = 0.f;
    sk[t] = Wk[t];
    float m = 0.f;
    for (int i = t; i < G; i += 256) m = fmaxf(m, fabsf(psi[i]));
#pragma unroll
    for (int o = 16; o; o >>= 1) m = fmaxf(m, __shfl_xor_sync(0xffffffffu, m, o));
    if ((t & 31) == 0) smax[t >> 5] = m;
    __syncthreads();
    if (t == 0) {
        float mm = 1e-12f;
        for (int i = 0; i < 8; ++i) mm = fmaxf(mm, smax[i]);
        g_amax = mm;
    }
    if (t < EDIM) {
        float a0 = 0.f, a1 = 0.f;
#pragma unroll 8
        for (int f = 0; f < FDIM; ++f) {
            float w = Wq[f * EDIM + t];
            a0 = fmaf(w, sk[f], a0);
            a1 = fmaf(w, sk[FDIM + f], a1);
        }
        g_dot[t * 2 + 0] = a0;
        g_dot[t * 2 + 1] = a1;
    }
}

// ---------------- kernel: grid-stride flat scan (4x float4 ILP) ---------------
__global__ void __launch_bounds__(512)
k_scan(const float4* __restrict__ oh4, const float* __restrict__ psi,
       const int* __restrict__ bs, int nvec) {
    int stride = gridDim.x * blockDim.x;
    for (int base = blockIdx.x * blockDim.x + threadIdx.x; base < nvec; base += 4 * stride) {
        float4 v[4];
        int ii[4];
#pragma unroll
        for (int u = 0; u < 4; ++u) {
            ii[u] = base + u * stride;
            if (ii[u] < nvec) v[u] = __ldcs(oh4 + ii[u]);
            else v[u] = make_float4(0.f, 0.f, 0.f, 0.f);
        }
#pragma unroll
        for (int u = 0; u < 4; ++u) {
            float vv[4] = {v[u].x, v[u].y, v[u].z, v[u].w};
#pragma unroll
            for (int c = 0; c < 4; ++c) {
                if (vv[c] != 0.f) {
                    unsigned f = 4u * (unsigned)ii[u] + (unsigned)c;
                    unsigned atom = f / 118u;
                    unsigned e = f - atom * 118u;
                    int g = bs[atom];
                    float p = psi[g];
                    int r = (p < 0.f) ? 1 : 0;
                    float qk = g_dot[e * 2 + r] * 0.08838834764831845f;  // 1/sqrt(128)
                    float y = (qk > 20.f) ? qk : log1pf(expf(qk));
                    g_y[atom] = y;
                    atomicAdd(&g_denom[g], y);
                }
            }
        }
    }
}

// ---------------- kernel: two-phase residual table + F'(0) --------------------
//   hlin = W1@wv;  h(a) = 0.5a*hlin + W1@s1(a*wv)
//   F(a) - a*F1 = W2 @ [ 0.5*(W1@s1(a*wv)) + s1(h(a)) ]
//   F1 = wv + 0.25*(W2@hlin)
__global__ void k_tab(const float* __restrict__ Wv, const float* __restrict__ W1,
                      const float* __restrict__ W2) {
    extern __shared__ float sm[];
    float* sW  = sm;                       // [128][WPITCH] (W1, then W2)
    float* swv = sW + FDIM * WPITCH;       // [128]
    float* shl = swv + FDIM;               // [128] hlin
    float* sSv = shl + FDIM;               // [8][128] s1(a_u*wv)
    float* sB  = sSv + 8 * FDIM;           // [8][128] bracket
    int t = threadIdx.x;
    int b = blockIdx.x;
    int r = (b >= 129) ? 1 : 0;
    int i0 = (b - r * 129) * 8;
    float sgn = r ? -1.f : 1.f;

    const float4* W1v = (const float4*)W1;
    for (int i = t; i < FDIM * 32; i += 128) {
        int row = i >> 5, c = (i & 31) * 4;
        float4 v = W1v[i];
        float* p = sW + row * WPITCH + c;
        p[0] = v.x; p[1] = v.y; p[2] = v.z; p[3] = v.w;
    }
    float wv = Wv[r * FDIM + t];
    swv[t] = wv;
    __syncthreads();

    const float* wrow = sW + t * WPITCH;
    float hlin;
    {
        float d0 = 0.f, d1 = 0.f, d2 = 0.f, d3 = 0.f;
#pragma unroll
        for (int k = 0; k < FDIM; k += 4) {
            d0 = fmaf(wrow[k],     swv[k],     d0);
            d1 = fmaf(wrow[k + 1], swv[k + 1], d1);
            d2 = fmaf(wrow[k + 2], swv[k + 2], d2);
            d3 = fmaf(wrow[k + 3], swv[k + 3], d3);
        }
        hlin = (d0 + d1) + (d2 + d3);
        shl[t] = hlin;
    }
    float amax = g_amax;
    float av[8];
#pragma unroll
    for (int u = 0; u < 8; ++u) {
        int i = i0 + u;
        float mag = (i == 0) ? (amax * (1.f / 8192.f)) : (amax * (float)i * (1.f / KTAB));
        av[u] = sgn * mag;
        sSv[u * FDIM + t] = s1f(av[u] * wv);
    }
    __syncthreads();

    for (int u = 0; u < 8; ++u) {
        if (i0 + u > KTAB) break;
        const float* sv = sSv + u * FDIM;
        float d0 = 0.f, d1 = 0.f, d2 = 0.f, d3 = 0.f;
#pragma unroll
        for (int k = 0; k < FDIM; k += 4) {
            d0 = fmaf(wrow[k],     sv[k],     d0);
            d1 = fmaf(wrow[k + 1], sv[k + 1], d1);
            d2 = fmaf(wrow[k + 2], sv[k + 2], d2);
            d3 = fmaf(wrow[k + 3], sv[k + 3], d3);
        }
        float tt = (d0 + d1) + (d2 + d3);
        float h = fmaf(0.5f * av[u], hlin, tt);
        sB[u * FDIM + t] = fmaf(0.5f, tt, s1f(h));
    }
    __syncthreads();

    const float4* W2v = (const float4*)W2;
    for (int i = t; i < FDIM * 32; i += 128) {
        int row = i >> 5, c = (i & 31) * 4;
        float4 v = W2v[i];
        float* p = sW + row * WPITCH + c;
        p[0] = v.x; p[1] = v.y; p[2] = v.z; p[3] = v.w;
    }
    __syncthreads();

    if (i0 == 0) {
        float d0 = 0.f, d1 = 0.f, d2 = 0.f, d3 = 0.f;
#pragma unroll
        for (int k = 0; k < FDIM; k += 4) {
            d0 = fmaf(wrow[k],     shl[k],     d0);
            d1 = fmaf(wrow[k + 1], shl[k + 1], d1);
            d2 = fmaf(wrow[k + 2], shl[k + 2], d2);
            d3 = fmaf(wrow[k + 3], shl[k + 3], d3);
        }
        g_lin[r * FDIM + t] = fmaf(0.25f, (d0 + d1) + (d2 + d3), wv);
    }
    for (int u = 0; u < 8; ++u) {
        int i = i0 + u;
        if (i > KTAB) break;
        const float* bv = sB + u * FDIM;
        float e0 = 0.f, e1 = 0.f, e2 = 0.f, e3 = 0.f;
#pragma unroll
        for (int k = 0; k < FDIM; k += 4) {
            e0 = fmaf(wrow[k],     bv[k],     e0);
            e1 = fmaf(wrow[k + 1], bv[k + 1], e1);
            e2 = fmaf(wrow[k + 2], bv[k + 2], e2);
            e3 = fmaf(wrow[k + 3], bv[k + 3], e3);
        }
        float resid = (e0 + e1) + (e2 + e3);
        g_tabh[r][i][t] = __float2half(resid / (av[u] * av[u]));
    }
}

// ---------------- kernel: per-atom attention scalar ---------------------------
__global__ void __launch_bounds__(256)
k_att(const float* __restrict__ psi, const int* __restrict__ bs, int N) {
    int n = blockIdx.x * blockDim.x + threadIdx.x;
    if (n >= N) return;
    int g = bs[n];
    float p = psi[g];
    g_att[n] = p * g_y[n] / (g_denom[g] + 1e-6f);
}

// ---------------- kernel: persistent warp-per-atom lookup + epilogue ----------
__global__ void __launch_bounds__(256)
k_out(float* __restrict__ out, int N) {
    int lane = threadIdx.x & 31;
    int gw = (blockIdx.x * blockDim.x + threadIdx.x) >> 5;
    int nwarps = (gridDim.x * blockDim.x) >> 5;
    // F1 for both branches in registers, loaded once per thread
    float4 f1a = ((const float4*)g_lin)[lane];
    float4 f1b = ((const float4*)(g_lin + FDIM))[lane];
    float scale = (float)KTAB / g_amax;

    for (int n0 = gw; n0 < N; n0 += 2 * nwarps) {
        int n1 = n0 + nwarps;
        float att0 = g_att[n0];
        float att1 = (n1 < N) ? g_att[n1] : 0.f;
        int r0 = (att0 < 0.f) ? 1 : 0;
        int r1 = (att1 < 0.f) ? 1 : 0;
        int j0 = __float2int_rn(fabsf(att0) * scale); if (j0 > KTAB) j0 = KTAB;
        int j1 = __float2int_rn(fabsf(att1) * scale); if (j1 > KTAB) j1 = KTAB;
        uint2 raw0 = __ldg((const uint2*)(&g_tabh[r0][j0][0]) + lane);
        uint2 raw1 = (n1 < N) ? __ldg((const uint2*)(&g_tabh[r1][j1][0]) + lane)
                              : make_uint2(0u, 0u);
        {
            float2 a01 = __half22float2(*(const __half2*)&raw0.x);
            float2 a23 = __half22float2(*(const __half2*)&raw0.y);
            float4 f1 = r0 ? f1b : f1a;
            float att2 = att0 * att0;
            float4 o;
            o.x = fmaf(att0, f1.x, att2 * a01.x);
            o.y = fmaf(att0, f1.y, att2 * a01.y);
            o.z = fmaf(att0, f1.z, att2 * a23.x);
            o.w = fmaf(att0, f1.w, att2 * a23.y);
            __stcs((float4*)out + (size_t)n0 * 32 + lane, o);
        }
        if (n1 < N) {
            float2 a01 = __half22float2(*(const __half2*)&raw1.x);
            float2 a23 = __half22float2(*(const __half2*)&raw1.y);
            float4 f1 = r1 ? f1b : f1a;
            float att2 = att1 * att1;
            float4 o;
            o.x = fmaf(att1, f1.x, att2 * a01.x);
            o.y = fmaf(att1, f1.y, att2 * a01.y);
            o.z = fmaf(att1, f1.z, att2 * a23.x);
            o.w = fmaf(att1, f1.w, att2 * a23.y);
            __stcs((float4*)out + (size_t)n1 * 32 + lane, o);
        }
    }
}

// ---------------- launch ----------------
extern "C" void kernel_launch(void* const* d_in, const int* in_sizes, int n_in,
                              void* d_out, int out_size) {
    const float* oh  = (const float*)d_in[0];
    const float* psi = (const float*)d_in[1];
    const float* Wq  = (const float*)d_in[2];
    const float* Wk  = (const float*)d_in[3];
    const float* Wv  = (const float*)d_in[4];
    const float* W1  = (const float*)d_in[5];
    const float* W2  = (const float*)d_in[6];
    const int*   bs  = (const int*)d_in[7];
    int N = in_sizes[7];
    int G = in_sizes[1];
    float* out = (float*)d_out;

    const int tab_smem = (FDIM * WPITCH + 2 * FDIM + 16 * FDIM) * 4;   // ~75 KB
    cudaFuncSetAttribute(k_tab, cudaFuncAttributeMaxDynamicSharedMemorySize, tab_smem);

    int nvec = (N * EDIM) / 4;                // N*118 divisible by 4

    k_prep<<<1, 256>>>(Wq, Wk, psi, G);
    k_scan<<<592, 512>>>((const float4*)oh, psi, bs, nvec);
    k_tab<<<258, 128, tab_smem>>>(Wv, W1, W2);
    k_att<<<(N + 255) / 256, 256>>>(psi, bs, N);
    k_out<<<1184, 256>>>(out, N);
}